// round 15
// baseline (speedup 1.0000x reference)
#include <cuda_runtime.h>
#include <cuda_fp16.h>
#include <cstdint>
#include <math.h>

// Problem constants
#define BATCH 4
#define SEQ   1024
#define DIM   1024
#define NHEAD 16
#define HDIM  64
#define MROWS (BATCH*SEQ)   // 4096
#define ATTN_SCALE 0.125f
#define LN_EPS 1e-5f

// Scratch (device globals)
__device__ __half g_Xh[MROWS*DIM];
__device__ __half g_Wh[4*DIM*DIM];
__device__ __half g_Qh[MROWS*DIM];
__device__ __half g_Kh[MROWS*DIM];
__device__ __half g_Vh[MROWS*DIM];
__device__ __half g_Oh[MROWS*DIM];
__device__ __half g_Fh[3*MROWS*DIM];      // fp16 QKV GEMM outputs
__device__ float  g_F [MROWS*DIM];        // fp32 Wo GEMM output

// ---------------------------------------------------------------------------
// helpers
// ---------------------------------------------------------------------------
__device__ __forceinline__ void cpasync16(uint32_t dst, const void* src) {
    asm volatile("cp.async.cg.shared.global [%0], [%1], 16;"
                 :: "r"(dst), "l"(src) : "memory");
}

__device__ __forceinline__ void mma_f16(float* d, const uint32_t* a, const uint32_t* b) {
    asm volatile(
        "mma.sync.aligned.m16n8k16.row.col.f32.f16.f16.f32 "
        "{%0,%1,%2,%3}, {%4,%5,%6,%7}, {%8,%9}, {%0,%1,%2,%3};"
        : "+f"(d[0]), "+f"(d[1]), "+f"(d[2]), "+f"(d[3])
        : "r"(a[0]), "r"(a[1]), "r"(a[2]), "r"(a[3]), "r"(b[0]), "r"(b[1]));
}

__device__ __forceinline__ void ldsm4(uint32_t* r, uint32_t a) {
    asm volatile("ldmatrix.sync.aligned.m8n8.x4.shared.b16 {%0,%1,%2,%3}, [%4];"
                 : "=r"(r[0]), "=r"(r[1]), "=r"(r[2]), "=r"(r[3]) : "r"(a));
}
__device__ __forceinline__ void ldsm4t(uint32_t* r, uint32_t a) {
    asm volatile("ldmatrix.sync.aligned.m8n8.x4.trans.shared.b16 {%0,%1,%2,%3}, [%4];"
                 : "=r"(r[0]), "=r"(r[1]), "=r"(r[2]), "=r"(r[3]) : "r"(a));
}

__device__ __forceinline__ uint32_t hex2_2(float a, float b) {
    __half2 h = __floats2half2_rn(a, b);
    uint32_t r;
    asm("ex2.approx.f16x2 %0, %1;" : "=r"(r) : "r"(*(uint32_t*)&h));
    return r;
}

// ---------------------------------------------------------------------------
// merged fp32 -> fp16 conversion pre-pass, 4 float4 per thread (MLP=4)
// ---------------------------------------------------------------------------
#define XN4 (MROWS*DIM/4)       // 1<<20
#define WN4 (DIM*DIM/4)         // 1<<18
#define CONV_TOT (XN4 + 4*WN4)  // 2M float4

__global__ __launch_bounds__(256) void conv_h(
    const float4* __restrict__ x,
    const float4* __restrict__ w0, const float4* __restrict__ w1,
    const float4* __restrict__ w2, const float4* __restrict__ w3)
{
    const int base = blockIdx.x * 1024 + threadIdx.x;
    float4 v[4];
    uint2* dst[4];
    #pragma unroll
    for (int k = 0; k < 4; k++) {
        int i = base + k * 256;
        if (i < XN4) {
            v[k] = x[i];
            dst[k] = (uint2*)g_Xh + i;
        } else {
            int j = i - XN4;
            int w = j >> 18;
            int o = j & (WN4 - 1);
            v[k] = (w == 0 ? w0 : w == 1 ? w1 : w == 2 ? w2 : w3)[o];
            dst[k] = (uint2*)g_Wh + j;
        }
    }
    #pragma unroll
    for (int k = 0; k < 4; k++) {
        __half2 h0 = __floats2half2_rn(v[k].x, v[k].y);
        __half2 h1 = __floats2half2_rn(v[k].z, v[k].w);
        uint2 o2; o2.x = *(uint32_t*)&h0; o2.y = *(uint32_t*)&h1;
        *dst[k] = o2;
    }
}

// ---------------------------------------------------------------------------
// fp16 tensor-core GEMM: CTA tile 128x128, warp tile 32x64, BK=64,
// 3-stage cp.async, 2 CTA/SM, register double-buffered fragments.
// ---------------------------------------------------------------------------
#define GPADH 72
#define GSTAGE_H (2 * 128 * GPADH)
#define GSTAGE_B (GSTAGE_H * 2)          // 36864 bytes
#define GNSTAGE 3
#define GNKITER (DIM / 64)               // 16
#define GEMM_SMEM (GNSTAGE * GSTAGE_B)   // 110592

__device__ __forceinline__ void load_stage_h(uint32_t sbase, int s,
                                             const __half* __restrict__ A,
                                             const __half* __restrict__ W,
                                             int m0, int n0, int kc, int tid) {
    uint32_t dst0 = sbase + (uint32_t)s * GSTAGE_B;
    #pragma unroll
    for (int i = 0; i < 8; i++) {
        int c   = i * 256 + tid;
        int row = (c & 1023) >> 3;
        int q   = c & 7;
        const __half* src = (c < 1024 ? A + (size_t)(m0 + row) * DIM
                                      : W + (size_t)(n0 + row) * DIM)
                            + kc * 64 + q * 8;
        uint32_t d = dst0 + (uint32_t)((c < 1024 ? 0 : 128 * GPADH) + row * GPADH + q * 8) * 2u;
        cpasync16(d, src);
    }
}

template <typename OutT>
__global__ __launch_bounds__(256, 2) void gemm_h(
    const __half* __restrict__ A, const __half* __restrict__ Wbase,
    const float* __restrict__ b0, const float* __restrict__ b1,
    const float* __restrict__ b2, OutT* __restrict__ Cbase)
{
    extern __shared__ __half smh[];
    const uint32_t sbase = (uint32_t)__cvta_generic_to_shared(smh);

    const int z = blockIdx.z;
    const __half* W = Wbase + (size_t)z * DIM * DIM;
    const float* bias = (z == 0) ? b0 : (z == 1) ? b1 : b2;
    OutT* C = Cbase + (size_t)z * MROWS * DIM;

    const int tid  = threadIdx.x;
    const int wid  = tid >> 5;
    const int lane = tid & 31;
    const int g    = lane >> 2;
    const int tg   = lane & 3;
    const int m0 = blockIdx.y * 128;
    const int n0 = blockIdx.x * 128;
    const int wm = (wid & 3) * 32;
    const int wn = (wid >> 2) * 64;

    const int t7   = lane & 7;
    const int aRow = t7 + ((lane >> 3) & 1) * 8;
    const int aCol = (lane >> 4) * 8;
    const int bRow = ((lane >> 4) & 1) * 8 + t7;
    const int bCol = ((lane >> 3) & 1) * 8;

    float acc[2][8][4];
    #pragma unroll
    for (int mi = 0; mi < 2; mi++)
        #pragma unroll
        for (int ni = 0; ni < 8; ni++)
            #pragma unroll
            for (int r = 0; r < 4; r++) acc[mi][ni][r] = 0.f;

    load_stage_h(sbase, 0, A, W, m0, n0, 0, tid);
    asm volatile("cp.async.commit_group;" ::: "memory");
    load_stage_h(sbase, 1, A, W, m0, n0, 1, tid);
    asm volatile("cp.async.commit_group;" ::: "memory");

    for (int c = 0; c < GNKITER; c++) {
        const int s = c % GNSTAGE;
        asm volatile("cp.async.wait_group 1;" ::: "memory");
        __syncthreads();

        const int pc = c + 2;
        if (pc < GNKITER)
            load_stage_h(sbase, pc % GNSTAGE, A, W, m0, n0, pc, tid);
        asm volatile("cp.async.commit_group;" ::: "memory");

        const uint32_t sA = sbase + s * GSTAGE_B;
        const uint32_t sB = sA + 128 * GPADH * 2;

        uint32_t a[2][2][4], b[2][4][4];
        #pragma unroll
        for (int mi = 0; mi < 2; mi++)
            ldsm4(a[0][mi], sA + (uint32_t)((wm + mi*16 + aRow) * GPADH + aCol) * 2);
        #pragma unroll
        for (int nj = 0; nj < 4; nj++)
            ldsm4(b[0][nj], sB + (uint32_t)((wn + nj*16 + bRow) * GPADH + bCol) * 2);

        #pragma unroll
        for (int kk = 0; kk < 4; kk++) {
            const int cur = kk & 1, nxt = cur ^ 1;
            if (kk < 3) {
                const int kh = (kk + 1) * 16;
                #pragma unroll
                for (int mi = 0; mi < 2; mi++)
                    ldsm4(a[nxt][mi], sA + (uint32_t)((wm + mi*16 + aRow) * GPADH + kh + aCol) * 2);
                #pragma unroll
                for (int nj = 0; nj < 4; nj++)
                    ldsm4(b[nxt][nj], sB + (uint32_t)((wn + nj*16 + bRow) * GPADH + kh + bCol) * 2);
            }
            #pragma unroll
            for (int mi = 0; mi < 2; mi++)
                #pragma unroll
                for (int nj = 0; nj < 4; nj++) {
                    mma_f16(acc[mi][2*nj],   a[cur][mi], &b[cur][nj][0]);
                    mma_f16(acc[mi][2*nj+1], a[cur][mi], &b[cur][nj][2]);
                }
        }
    }

    #pragma unroll
    for (int ni = 0; ni < 8; ni++) {
        const int col = n0 + wn + ni * 8 + tg * 2;
        const float c0 = bias[col], c1 = bias[col + 1];
        #pragma unroll
        for (int mi = 0; mi < 2; mi++) {
            const int row = m0 + wm + mi * 16 + g;
            if constexpr (sizeof(OutT) == 2) {
                *(__half2*)((__half*)C + (size_t)row * DIM + col) =
                    __floats2half2_rn(acc[mi][ni][0] + c0, acc[mi][ni][1] + c1);
                *(__half2*)((__half*)C + (size_t)(row + 8) * DIM + col) =
                    __floats2half2_rn(acc[mi][ni][2] + c0, acc[mi][ni][3] + c1);
            } else {
                *(float2*)((float*)C + (size_t)row * DIM + col) =
                    make_float2(acc[mi][ni][0] + c0, acc[mi][ni][1] + c1);
                *(float2*)((float*)C + (size_t)(row + 8) * DIM + col) =
                    make_float2(acc[mi][ni][2] + c0, acc[mi][ni][3] + c1);
            }
        }
    }
}

// ---------------------------------------------------------------------------
// warp-per-row LayerNorm: fp16 input (QKV path), fp16 output
// ---------------------------------------------------------------------------
__global__ __launch_bounds__(256) void ln3_h(
    const float* __restrict__ qg, const float* __restrict__ qb,
    const float* __restrict__ kg, const float* __restrict__ kb_,
    const float* __restrict__ vg, const float* __restrict__ vb)
{
    const int z = blockIdx.y;
    const __half* in  = g_Fh + (size_t)z * MROWS * DIM;
    __half* out       = (z == 0) ? g_Qh : (z == 1) ? g_Kh : g_Vh;
    const float* gam  = (z == 0) ? qg : (z == 1) ? kg : vg;
    const float* bet  = (z == 0) ? qb : (z == 1) ? kb_ : vb;
    const float scale = (z == 0) ? ATTN_SCALE : 1.0f;

    const int wid  = threadIdx.x >> 5;
    const int lane = threadIdx.x & 31;
    const int row  = blockIdx.x * 8 + wid;

    const uint2* rp = (const uint2*)(in + (size_t)row * DIM);
    float4 v[8];
    float s = 0.f, ss = 0.f;
    #pragma unroll
    for (int j = 0; j < 8; j++) {
        uint2 hv = rp[j * 32 + lane];
        float2 f0 = __half22float2(*(__half2*)&hv.x);
        float2 f1 = __half22float2(*(__half2*)&hv.y);
        v[j] = make_float4(f0.x, f0.y, f1.x, f1.y);
        s  += v[j].x + v[j].y + v[j].z + v[j].w;
        ss += v[j].x*v[j].x + v[j].y*v[j].y + v[j].z*v[j].z + v[j].w*v[j].w;
    }
    #pragma unroll
    for (int o = 16; o > 0; o >>= 1) {
        s  += __shfl_xor_sync(0xffffffffu, s,  o);
        ss += __shfl_xor_sync(0xffffffffu, ss, o);
    }
    const float mu = s * (1.0f / DIM);
    const float rs = rsqrtf(ss * (1.0f / DIM) - mu * mu + LN_EPS);

    uint2* op = (uint2*)(out + (size_t)row * DIM);
    #pragma unroll
    for (int j = 0; j < 8; j++) {
        const float4 g4 = ((const float4*)gam)[j * 32 + lane];
        const float4 b4 = ((const float4*)bet)[j * 32 + lane];
        __half2 h0 = __floats2half2_rn(((v[j].x - mu) * rs * g4.x + b4.x) * scale,
                                       ((v[j].y - mu) * rs * g4.y + b4.y) * scale);
        __half2 h1 = __floats2half2_rn(((v[j].z - mu) * rs * g4.z + b4.z) * scale,
                                       ((v[j].w - mu) * rs * g4.w + b4.w) * scale);
        uint2 o2; o2.x = *(uint32_t*)&h0; o2.y = *(uint32_t*)&h1;
        op[j * 32 + lane] = o2;
    }
}

// fp32 in -> fp32 out (final LN)
__global__ __launch_bounds__(256) void ln_f(
    const float* __restrict__ in, float* __restrict__ out,
    const float* __restrict__ gam, const float* __restrict__ bet)
{
    const int wid  = threadIdx.x >> 5;
    const int lane = threadIdx.x & 31;
    const int row  = blockIdx.x * 8 + wid;

    const float4* rp = (const float4*)(in + (size_t)row * DIM);
    float4 v[8];
    float s = 0.f, ss = 0.f;
    #pragma unroll
    for (int j = 0; j < 8; j++) {
        v[j] = rp[j * 32 + lane];
        s  += v[j].x + v[j].y + v[j].z + v[j].w;
        ss += v[j].x*v[j].x + v[j].y*v[j].y + v[j].z*v[j].z + v[j].w*v[j].w;
    }
    #pragma unroll
    for (int o = 16; o > 0; o >>= 1) {
        s  += __shfl_xor_sync(0xffffffffu, s,  o);
        ss += __shfl_xor_sync(0xffffffffu, ss, o);
    }
    const float mu = s * (1.0f / DIM);
    const float rs = rsqrtf(ss * (1.0f / DIM) - mu * mu + LN_EPS);

    float4* op = (float4*)(out + (size_t)row * DIM);
    #pragma unroll
    for (int j = 0; j < 8; j++) {
        const float4 g4 = ((const float4*)gam)[j * 32 + lane];
        const float4 b4 = ((const float4*)bet)[j * 32 + lane];
        float4 o;
        o.x = (v[j].x - mu) * rs * g4.x + b4.x;
        o.y = (v[j].y - mu) * rs * g4.y + b4.y;
        o.z = (v[j].z - mu) * rs * g4.z + b4.z;
        o.w = (v[j].w - mu) * rs * g4.w + b4.w;
        op[j * 32 + lane] = o;
    }
}

// ---------------------------------------------------------------------------
// fp16 flash attention: 4 warps x 32 Q-rows, S-phase fused over shared K
// fragments; softmax/PV STAGGERED across groups so grp1's MUFU stream
// overlaps grp0's PV tensor work. K+V double buffered, one barrier/tile.
// ---------------------------------------------------------------------------
#define QKPH 72
#define AH_Q  0
#define AH_K0 (128*QKPH)
#define AH_K1 (2*128*QKPH)
#define AH_V0 (3*128*QKPH)
#define AH_V1 (4*128*QKPH)
#define ATTN_SMEM (5*128*QKPH*2)         // 92160 bytes

#define L2E   1.4426950408889634f
#define EOFF  (-0.42695040888963f)
#define ONES2 0x3C003C00u

__global__ __launch_bounds__(128, 2) void attn_h()
{
    extern __shared__ __half smh[];
    const uint32_t sb = (uint32_t)__cvta_generic_to_shared(smh);

    const int bh = blockIdx.y;
    const int b  = bh >> 4;
    const int h  = bh & 15;
    const int q0 = blockIdx.x * 128;
    const int tid  = threadIdx.x;
    const int wid  = tid >> 5;
    const int lane = tid & 31;
    const int g    = lane >> 2;
    const int tg   = lane & 3;
    const int wm   = wid * 32;

    const int t7   = lane & 7;
    const int aRow = t7 + ((lane >> 3) & 1) * 8;
    const int aCol = (lane >> 4) * 8;
    const int bRow = ((lane >> 4) & 1) * 8 + t7;
    const int bCol = ((lane >> 3) & 1) * 8;
    const int vRow = ((lane >> 3) & 1) * 8 + t7;
    const int vCol = (lane >> 4) * 8;

    const __half* Qg = g_Qh + ((size_t)b*SEQ + q0)*DIM + h*HDIM;
    const __half* Kg = g_Kh + (size_t)b*SEQ*DIM + h*HDIM;
    const __half* Vg = g_Vh + (size_t)b*SEQ*DIM + h*HDIM;

    #pragma unroll
    for (int i = 0; i < 8; i++) {
        int idx = i * 128 + tid;
        int r = idx >> 3, q = idx & 7;
        cpasync16(sb + (uint32_t)(AH_Q  + r*QKPH + q*8)*2, Qg + (size_t)r*DIM + q*8);
        cpasync16(sb + (uint32_t)(AH_K0 + r*QKPH + q*8)*2, Kg + (size_t)r*DIM + q*8);
        cpasync16(sb + (uint32_t)(AH_V0 + r*QKPH + q*8)*2, Vg + (size_t)r*DIM + q*8);
    }
    asm volatile("cp.async.commit_group;" ::: "memory");

    float oacc[2][8][4];
    #pragma unroll
    for (int grp = 0; grp < 2; grp++)
        #pragma unroll
        for (int ni = 0; ni < 8; ni++)
            #pragma unroll
            for (int j = 0; j < 4; j++) oacc[grp][ni][j] = 0.f;
    float lsum[2][4] = {{0.f,0.f,0.f,0.f},{0.f,0.f,0.f,0.f}};
    const uint32_t onesb[2] = { ONES2, ONES2 };

    const int NT = SEQ / 128;
    for (int kt = 0; kt < NT; kt++) {
        asm volatile("cp.async.wait_group 0;" ::: "memory");
        __syncthreads();

        if (kt + 1 < NT) {
            const __half* Kn = Kg + (size_t)(kt + 1) * 128 * DIM;
            const __half* Vn = Vg + (size_t)(kt + 1) * 128 * DIM;
            const uint32_t kdst = ((kt + 1) & 1) ? AH_K1 : AH_K0;
            const uint32_t vdst = ((kt + 1) & 1) ? AH_V1 : AH_V0;
            #pragma unroll
            for (int i = 0; i < 8; i++) {
                int idx = i * 128 + tid;
                int r = idx >> 3, q = idx & 7;
                cpasync16(sb + (uint32_t)(kdst + r*QKPH + q*8)*2, Kn + (size_t)r*DIM + q*8);
                cpasync16(sb + (uint32_t)(vdst + r*QKPH + q*8)*2, Vn + (size_t)r*DIM + q*8);
            }
        }
        asm volatile("cp.async.commit_group;" ::: "memory");

        const uint32_t ksrc = (kt & 1) ? AH_K1 : AH_K0;
        const uint32_t vsrc = (kt & 1) ? AH_V1 : AH_V0;

        // ---- S = Q K^T : both 16-row groups fused over shared K fragments ----
        float sacc[2][16][4];
        #pragma unroll
        for (int grp = 0; grp < 2; grp++)
            #pragma unroll
            for (int ni = 0; ni < 16; ni++)
                #pragma unroll
                for (int j = 0; j < 4; j++) sacc[grp][ni][j] = 0.f;

        #pragma unroll
        for (int kk = 0; kk < 4; kk++) {
            const int kh = kk * 16;
            uint32_t aq0[4], aq1[4];
            ldsm4(aq0, sb + (uint32_t)(AH_Q + (wm + aRow)*QKPH + kh + aCol) * 2);
            ldsm4(aq1, sb + (uint32_t)(AH_Q + (wm + 16 + aRow)*QKPH + kh + aCol) * 2);
            #pragma unroll
            for (int nj = 0; nj < 8; nj++) {
                uint32_t bk[4];
                ldsm4(bk, sb + (uint32_t)(ksrc + (nj*16 + bRow)*QKPH + kh + bCol) * 2);
                mma_f16(sacc[0][2*nj],   aq0, &bk[0]);
                mma_f16(sacc[0][2*nj+1], aq0, &bk[2]);
                mma_f16(sacc[1][2*nj],   aq1, &bk[0]);
                mma_f16(sacc[1][2*nj+1], aq1, &bk[2]);
            }
        }

        // ---- softmax grp0 ----
        uint32_t pa[2][8][4];
        #pragma unroll
        for (int j = 0; j < 8; j++) {
            pa[0][j][0] = hex2_2(fmaf(sacc[0][2*j][0],   L2E, EOFF), fmaf(sacc[0][2*j][1],   L2E, EOFF));
            pa[0][j][1] = hex2_2(fmaf(sacc[0][2*j][2],   L2E, EOFF), fmaf(sacc[0][2*j][3],   L2E, EOFF));
            pa[0][j][2] = hex2_2(fmaf(sacc[0][2*j+1][0], L2E, EOFF), fmaf(sacc[0][2*j+1][1], L2E, EOFF));
            pa[0][j][3] = hex2_2(fmaf(sacc[0][2*j+1][2], L2E, EOFF), fmaf(sacc[0][2*j+1][3], L2E, EOFF));
            mma_f16(lsum[0], pa[0][j], onesb);
        }

        // ---- PV grp0 interleaved with softmax grp1 (MUFU overlaps tensor) ----
        #pragma unroll
        for (int j = 0; j < 8; j++) {
            pa[1][j][0] = hex2_2(fmaf(sacc[1][2*j][0],   L2E, EOFF), fmaf(sacc[1][2*j][1],   L2E, EOFF));
            pa[1][j][1] = hex2_2(fmaf(sacc[1][2*j][2],   L2E, EOFF), fmaf(sacc[1][2*j][3],   L2E, EOFF));
            pa[1][j][2] = hex2_2(fmaf(sacc[1][2*j+1][0], L2E, EOFF), fmaf(sacc[1][2*j+1][1], L2E, EOFF));
            pa[1][j][3] = hex2_2(fmaf(sacc[1][2*j+1][2], L2E, EOFF), fmaf(sacc[1][2*j+1][3], L2E, EOFF));
            mma_f16(lsum[1], pa[1][j], onesb);
            #pragma unroll
            for (int nj = 0; nj < 4; nj++) {
                uint32_t bv[4];
                ldsm4t(bv, sb + (uint32_t)(vsrc + (j*16 + vRow)*QKPH + nj*16 + vCol) * 2);
                mma_f16(oacc[0][2*nj],   pa[0][j], &bv[0]);
                mma_f16(oacc[0][2*nj+1], pa[0][j], &bv[2]);
            }
        }

        // ---- PV grp1 ----
        #pragma unroll
        for (int j = 0; j < 8; j++) {
            #pragma unroll
            for (int nj = 0; nj < 4; nj++) {
                uint32_t bv[4];
                ldsm4t(bv, sb + (uint32_t)(vsrc + (j*16 + vRow)*QKPH + nj*16 + vCol) * 2);
                mma_f16(oacc[1][2*nj],   pa[1][j], &bv[0]);
                mma_f16(oacc[1][2*nj+1], pa[1][j], &bv[2]);
            }
        }
    }

    __half* Og = g_Oh + ((size_t)b*SEQ + q0)*DIM + h*HDIM;
    #pragma unroll
    for (int grp = 0; grp < 2; grp++) {
        const float inv0 = 1.0f / lsum[grp][0];
        const float inv1 = 1.0f / lsum[grp][2];
        const int rowb = wm + grp * 16;
        #pragma unroll
        for (int ni = 0; ni < 8; ni++) {
            const int col = ni * 8 + 2 * tg;
            *(__half2*)(Og + (size_t)(rowb + g)*DIM + col) =
                __floats2half2_rn(oacc[grp][ni][0]*inv0, oacc[grp][ni][1]*inv0);
            *(__half2*)(Og + (size_t)(rowb + 8 + g)*DIM + col) =
                __floats2half2_rn(oacc[grp][ni][2]*inv1, oacc[grp][ni][3]*inv1);
        }
    }
}

// ---------------------------------------------------------------------------
extern "C" void kernel_launch(void* const* d_in, const int* in_sizes, int n_in,
                              void* d_out, int out_size)
{
    const float* x    = (const float*)d_in[0];
    const float* Wq   = (const float*)d_in[1];
    const float* bq   = (const float*)d_in[2];
    const float* Wk   = (const float*)d_in[3];
    const float* bk   = (const float*)d_in[4];
    const float* Wv   = (const float*)d_in[5];
    const float* bv   = (const float*)d_in[6];
    const float* Wo   = (const float*)d_in[7];
    const float* bo   = (const float*)d_in[8];
    const float* qn_g = (const float*)d_in[9];
    const float* qn_b = (const float*)d_in[10];
    const float* kn_g = (const float*)d_in[11];
    const float* kn_b = (const float*)d_in[12];
    const float* vn_g = (const float*)d_in[13];
    const float* vn_b = (const float*)d_in[14];
    const float* on_g = (const float*)d_in[15];
    const float* on_b = (const float*)d_in[16];
    float* out = (float*)d_out;

    __half *Xh, *Wh, *Oh, *Fh;
    float *F;
    cudaGetSymbolAddress((void**)&Xh, g_Xh);
    cudaGetSymbolAddress((void**)&Wh, g_Wh);
    cudaGetSymbolAddress((void**)&Oh, g_Oh);
    cudaGetSymbolAddress((void**)&Fh, g_Fh);
    cudaGetSymbolAddress((void**)&F,  g_F);

    conv_h<<<CONV_TOT / 1024, 256>>>((const float4*)x, (const float4*)Wq,
                                     (const float4*)Wk, (const float4*)Wv,
                                     (const float4*)Wo);

    cudaFuncSetAttribute(gemm_h<__half>, cudaFuncAttributeMaxDynamicSharedMemorySize, GEMM_SMEM);
    cudaFuncSetAttribute(gemm_h<float>,  cudaFuncAttributeMaxDynamicSharedMemorySize, GEMM_SMEM);
    cudaFuncSetAttribute(attn_h, cudaFuncAttributeMaxDynamicSharedMemorySize, ATTN_SMEM);

    gemm_h<__half><<<dim3(DIM/128, MROWS/128, 3), 256, GEMM_SMEM>>>(Xh, Wh, bq, bk, bv, Fh);
    ln3_h<<<dim3(MROWS/8, 3), 256>>>(qn_g, qn_b, kn_g, kn_b, vn_g, vn_b);
    attn_h<<<dim3(SEQ/128, BATCH*NHEAD), 128, ATTN_SMEM>>>();
    gemm_h<float><<<dim3(DIM/128, MROWS/128, 1), 256, GEMM_SMEM>>>(
        Oh, Wh + 3*(size_t)DIM*DIM, bo, bo, bo, F);
    ln_f<<<MROWS/8, 256>>>(F, out, on_g, on_b);
}

// round 16
// speedup vs baseline: 1.0246x; 1.0246x over previous
#include <cuda_runtime.h>
#include <cuda_fp16.h>
#include <cstdint>
#include <math.h>

// Problem constants
#define BATCH 4
#define SEQ   1024
#define DIM   1024
#define NHEAD 16
#define HDIM  64
#define MROWS (BATCH*SEQ)   // 4096
#define ATTN_SCALE 0.125f
#define LN_EPS 1e-5f

// Scratch (device globals)
__device__ __half g_Xh[MROWS*DIM];
__device__ __half g_Wh[4*DIM*DIM];
__device__ __half g_Qh[MROWS*DIM];
__device__ __half g_Kh[MROWS*DIM];
__device__ __half g_Vh[MROWS*DIM];
__device__ __half g_Oh[MROWS*DIM];
__device__ __half g_Fh[3*MROWS*DIM];      // fp16 QKV GEMM outputs
__device__ float  g_F [MROWS*DIM];        // fp32 Wo GEMM output

// ---------------------------------------------------------------------------
// helpers
// ---------------------------------------------------------------------------
__device__ __forceinline__ void cpasync16(uint32_t dst, const void* src) {
    asm volatile("cp.async.cg.shared.global [%0], [%1], 16;"
                 :: "r"(dst), "l"(src) : "memory");
}

__device__ __forceinline__ void mma_f16(float* d, const uint32_t* a, const uint32_t* b) {
    asm volatile(
        "mma.sync.aligned.m16n8k16.row.col.f32.f16.f16.f32 "
        "{%0,%1,%2,%3}, {%4,%5,%6,%7}, {%8,%9}, {%0,%1,%2,%3};"
        : "+f"(d[0]), "+f"(d[1]), "+f"(d[2]), "+f"(d[3])
        : "r"(a[0]), "r"(a[1]), "r"(a[2]), "r"(a[3]), "r"(b[0]), "r"(b[1]));
}

__device__ __forceinline__ void ldsm4(uint32_t* r, uint32_t a) {
    asm volatile("ldmatrix.sync.aligned.m8n8.x4.shared.b16 {%0,%1,%2,%3}, [%4];"
                 : "=r"(r[0]), "=r"(r[1]), "=r"(r[2]), "=r"(r[3]) : "r"(a));
}
__device__ __forceinline__ void ldsm4t(uint32_t* r, uint32_t a) {
    asm volatile("ldmatrix.sync.aligned.m8n8.x4.trans.shared.b16 {%0,%1,%2,%3}, [%4];"
                 : "=r"(r[0]), "=r"(r[1]), "=r"(r[2]), "=r"(r[3]) : "r"(a));
}

__device__ __forceinline__ uint32_t hex2_2(float a, float b) {
    __half2 h = __floats2half2_rn(a, b);
    uint32_t r;
    asm("ex2.approx.f16x2 %0, %1;" : "=r"(r) : "r"(*(uint32_t*)&h));
    return r;
}

// PDL: wait for upstream kernel's results to be visible
__device__ __forceinline__ void pdl_wait() {
#if __CUDA_ARCH__ >= 900
    cudaGridDependencySynchronize();
#endif
}

// ---------------------------------------------------------------------------
// merged fp32 -> fp16 conversion pre-pass, 4 float4 per thread (MLP=4)
// ---------------------------------------------------------------------------
#define XN4 (MROWS*DIM/4)       // 1<<20
#define WN4 (DIM*DIM/4)         // 1<<18
#define CONV_TOT (XN4 + 4*WN4)  // 2M float4

__global__ __launch_bounds__(256) void conv_h(
    const float4* __restrict__ x,
    const float4* __restrict__ w0, const float4* __restrict__ w1,
    const float4* __restrict__ w2, const float4* __restrict__ w3)
{
    const int base = blockIdx.x * 1024 + threadIdx.x;
    float4 v[4];
    uint2* dst[4];
    #pragma unroll
    for (int k = 0; k < 4; k++) {
        int i = base + k * 256;
        if (i < XN4) {
            v[k] = x[i];
            dst[k] = (uint2*)g_Xh + i;
        } else {
            int j = i - XN4;
            int w = j >> 18;
            int o = j & (WN4 - 1);
            v[k] = (w == 0 ? w0 : w == 1 ? w1 : w == 2 ? w2 : w3)[o];
            dst[k] = (uint2*)g_Wh + j;
        }
    }
    #pragma unroll
    for (int k = 0; k < 4; k++) {
        __half2 h0 = __floats2half2_rn(v[k].x, v[k].y);
        __half2 h1 = __floats2half2_rn(v[k].z, v[k].w);
        uint2 o2; o2.x = *(uint32_t*)&h0; o2.y = *(uint32_t*)&h1;
        *dst[k] = o2;
    }
}

// ---------------------------------------------------------------------------
// fp16 tensor-core GEMM: CTA tile 128x128, warp tile 32x64, BK=64,
// 3-stage cp.async, 2 CTA/SM, register double-buffered fragments.
// ---------------------------------------------------------------------------
#define GPADH 72
#define GSTAGE_H (2 * 128 * GPADH)
#define GSTAGE_B (GSTAGE_H * 2)          // 36864 bytes
#define GNSTAGE 3
#define GNKITER (DIM / 64)               // 16
#define GEMM_SMEM (GNSTAGE * GSTAGE_B)   // 110592

__device__ __forceinline__ void load_stage_h(uint32_t sbase, int s,
                                             const __half* __restrict__ A,
                                             const __half* __restrict__ W,
                                             int m0, int n0, int kc, int tid) {
    uint32_t dst0 = sbase + (uint32_t)s * GSTAGE_B;
    #pragma unroll
    for (int i = 0; i < 8; i++) {
        int c   = i * 256 + tid;
        int row = (c & 1023) >> 3;
        int q   = c & 7;
        const __half* src = (c < 1024 ? A + (size_t)(m0 + row) * DIM
                                      : W + (size_t)(n0 + row) * DIM)
                            + kc * 64 + q * 8;
        uint32_t d = dst0 + (uint32_t)((c < 1024 ? 0 : 128 * GPADH) + row * GPADH + q * 8) * 2u;
        cpasync16(d, src);
    }
}

template <typename OutT>
__global__ __launch_bounds__(256, 2) void gemm_h(
    const __half* __restrict__ A, const __half* __restrict__ Wbase,
    const float* __restrict__ b0, const float* __restrict__ b1,
    const float* __restrict__ b2, OutT* __restrict__ Cbase)
{
    extern __shared__ __half smh[];
    const uint32_t sbase = (uint32_t)__cvta_generic_to_shared(smh);

    const int z = blockIdx.z;
    const __half* W = Wbase + (size_t)z * DIM * DIM;
    const float* bias = (z == 0) ? b0 : (z == 1) ? b1 : b2;
    OutT* C = Cbase + (size_t)z * MROWS * DIM;

    const int tid  = threadIdx.x;
    const int wid  = tid >> 5;
    const int lane = tid & 31;
    const int g    = lane >> 2;
    const int tg   = lane & 3;
    const int m0 = blockIdx.y * 128;
    const int n0 = blockIdx.x * 128;
    const int wm = (wid & 3) * 32;
    const int wn = (wid >> 2) * 64;

    const int t7   = lane & 7;
    const int aRow = t7 + ((lane >> 3) & 1) * 8;
    const int aCol = (lane >> 4) * 8;
    const int bRow = ((lane >> 4) & 1) * 8 + t7;
    const int bCol = ((lane >> 3) & 1) * 8;

    float acc[2][8][4];
    #pragma unroll
    for (int mi = 0; mi < 2; mi++)
        #pragma unroll
        for (int ni = 0; ni < 8; ni++)
            #pragma unroll
            for (int r = 0; r < 4; r++) acc[mi][ni][r] = 0.f;

    pdl_wait();   // upstream results must be visible before loading

    load_stage_h(sbase, 0, A, W, m0, n0, 0, tid);
    asm volatile("cp.async.commit_group;" ::: "memory");
    load_stage_h(sbase, 1, A, W, m0, n0, 1, tid);
    asm volatile("cp.async.commit_group;" ::: "memory");

    for (int c = 0; c < GNKITER; c++) {
        const int s = c % GNSTAGE;
        asm volatile("cp.async.wait_group 1;" ::: "memory");
        __syncthreads();

        const int pc = c + 2;
        if (pc < GNKITER)
            load_stage_h(sbase, pc % GNSTAGE, A, W, m0, n0, pc, tid);
        asm volatile("cp.async.commit_group;" ::: "memory");

        const uint32_t sA = sbase + s * GSTAGE_B;
        const uint32_t sB = sA + 128 * GPADH * 2;

        uint32_t a[2][2][4], b[2][4][4];
        #pragma unroll
        for (int mi = 0; mi < 2; mi++)
            ldsm4(a[0][mi], sA + (uint32_t)((wm + mi*16 + aRow) * GPADH + aCol) * 2);
        #pragma unroll
        for (int nj = 0; nj < 4; nj++)
            ldsm4(b[0][nj], sB + (uint32_t)((wn + nj*16 + bRow) * GPADH + bCol) * 2);

        #pragma unroll
        for (int kk = 0; kk < 4; kk++) {
            const int cur = kk & 1, nxt = cur ^ 1;
            if (kk < 3) {
                const int kh = (kk + 1) * 16;
                #pragma unroll
                for (int mi = 0; mi < 2; mi++)
                    ldsm4(a[nxt][mi], sA + (uint32_t)((wm + mi*16 + aRow) * GPADH + kh + aCol) * 2);
                #pragma unroll
                for (int nj = 0; nj < 4; nj++)
                    ldsm4(b[nxt][nj], sB + (uint32_t)((wn + nj*16 + bRow) * GPADH + kh + bCol) * 2);
            }
            #pragma unroll
            for (int mi = 0; mi < 2; mi++)
                #pragma unroll
                for (int nj = 0; nj < 4; nj++) {
                    mma_f16(acc[mi][2*nj],   a[cur][mi], &b[cur][nj][0]);
                    mma_f16(acc[mi][2*nj+1], a[cur][mi], &b[cur][nj][2]);
                }
        }
    }

    #pragma unroll
    for (int ni = 0; ni < 8; ni++) {
        const int col = n0 + wn + ni * 8 + tg * 2;
        const float c0 = bias[col], c1 = bias[col + 1];
        #pragma unroll
        for (int mi = 0; mi < 2; mi++) {
            const int row = m0 + wm + mi * 16 + g;
            if constexpr (sizeof(OutT) == 2) {
                *(__half2*)((__half*)C + (size_t)row * DIM + col) =
                    __floats2half2_rn(acc[mi][ni][0] + c0, acc[mi][ni][1] + c1);
                *(__half2*)((__half*)C + (size_t)(row + 8) * DIM + col) =
                    __floats2half2_rn(acc[mi][ni][2] + c0, acc[mi][ni][3] + c1);
            } else {
                *(float2*)((float*)C + (size_t)row * DIM + col) =
                    make_float2(acc[mi][ni][0] + c0, acc[mi][ni][1] + c1);
                *(float2*)((float*)C + (size_t)(row + 8) * DIM + col) =
                    make_float2(acc[mi][ni][2] + c0, acc[mi][ni][3] + c1);
            }
        }
    }
}

// ---------------------------------------------------------------------------
// warp-per-row LayerNorm: fp16 input (QKV path), fp16 output
// ---------------------------------------------------------------------------
__global__ __launch_bounds__(256) void ln3_h(
    const float* __restrict__ qg, const float* __restrict__ qb,
    const float* __restrict__ kg, const float* __restrict__ kb_,
    const float* __restrict__ vg, const float* __restrict__ vb)
{
    const int z = blockIdx.y;
    const __half* in  = g_Fh + (size_t)z * MROWS * DIM;
    __half* out       = (z == 0) ? g_Qh : (z == 1) ? g_Kh : g_Vh;
    const float* gam  = (z == 0) ? qg : (z == 1) ? kg : vg;
    const float* bet  = (z == 0) ? qb : (z == 1) ? kb_ : vb;
    const float scale = (z == 0) ? ATTN_SCALE : 1.0f;

    const int wid  = threadIdx.x >> 5;
    const int lane = threadIdx.x & 31;
    const int row  = blockIdx.x * 8 + wid;

    pdl_wait();

    const uint2* rp = (const uint2*)(in + (size_t)row * DIM);
    float4 v[8];
    float s = 0.f, ss = 0.f;
    #pragma unroll
    for (int j = 0; j < 8; j++) {
        uint2 hv = rp[j * 32 + lane];
        float2 f0 = __half22float2(*(__half2*)&hv.x);
        float2 f1 = __half22float2(*(__half2*)&hv.y);
        v[j] = make_float4(f0.x, f0.y, f1.x, f1.y);
        s  += v[j].x + v[j].y + v[j].z + v[j].w;
        ss += v[j].x*v[j].x + v[j].y*v[j].y + v[j].z*v[j].z + v[j].w*v[j].w;
    }
    #pragma unroll
    for (int o = 16; o > 0; o >>= 1) {
        s  += __shfl_xor_sync(0xffffffffu, s,  o);
        ss += __shfl_xor_sync(0xffffffffu, ss, o);
    }
    const float mu = s * (1.0f / DIM);
    const float rs = rsqrtf(ss * (1.0f / DIM) - mu * mu + LN_EPS);

    uint2* op = (uint2*)(out + (size_t)row * DIM);
    #pragma unroll
    for (int j = 0; j < 8; j++) {
        const float4 g4 = ((const float4*)gam)[j * 32 + lane];
        const float4 b4 = ((const float4*)bet)[j * 32 + lane];
        __half2 h0 = __floats2half2_rn(((v[j].x - mu) * rs * g4.x + b4.x) * scale,
                                       ((v[j].y - mu) * rs * g4.y + b4.y) * scale);
        __half2 h1 = __floats2half2_rn(((v[j].z - mu) * rs * g4.z + b4.z) * scale,
                                       ((v[j].w - mu) * rs * g4.w + b4.w) * scale);
        uint2 o2; o2.x = *(uint32_t*)&h0; o2.y = *(uint32_t*)&h1;
        op[j * 32 + lane] = o2;
    }
}

// fp32 in -> fp32 out (final LN)
__global__ __launch_bounds__(256) void ln_f(
    const float* __restrict__ in, float* __restrict__ out,
    const float* __restrict__ gam, const float* __restrict__ bet)
{
    const int wid  = threadIdx.x >> 5;
    const int lane = threadIdx.x & 31;
    const int row  = blockIdx.x * 8 + wid;

    pdl_wait();

    const float4* rp = (const float4*)(in + (size_t)row * DIM);
    float4 v[8];
    float s = 0.f, ss = 0.f;
    #pragma unroll
    for (int j = 0; j < 8; j++) {
        v[j] = rp[j * 32 + lane];
        s  += v[j].x + v[j].y + v[j].z + v[j].w;
        ss += v[j].x*v[j].x + v[j].y*v[j].y + v[j].z*v[j].z + v[j].w*v[j].w;
    }
    #pragma unroll
    for (int o = 16; o > 0; o >>= 1) {
        s  += __shfl_xor_sync(0xffffffffu, s,  o);
        ss += __shfl_xor_sync(0xffffffffu, ss, o);
    }
    const float mu = s * (1.0f / DIM);
    const float rs = rsqrtf(ss * (1.0f / DIM) - mu * mu + LN_EPS);

    float4* op = (float4*)(out + (size_t)row * DIM);
    #pragma unroll
    for (int j = 0; j < 8; j++) {
        const float4 g4 = ((const float4*)gam)[j * 32 + lane];
        const float4 b4 = ((const float4*)bet)[j * 32 + lane];
        float4 o;
        o.x = (v[j].x - mu) * rs * g4.x + b4.x;
        o.y = (v[j].y - mu) * rs * g4.y + b4.y;
        o.z = (v[j].z - mu) * rs * g4.z + b4.z;
        o.w = (v[j].w - mu) * rs * g4.w + b4.w;
        op[j * 32 + lane] = o;
    }
}

// ---------------------------------------------------------------------------
// fp16 flash attention (R14 best schedule): 4 warps x 32 Q-rows, S fused over
// shared K fragments, grouped softmax, shared-V PV, K+V double buffered,
// one barrier per tile. 2 CTA/SM.
// ---------------------------------------------------------------------------
#define QKPH 72
#define AH_Q  0
#define AH_K0 (128*QKPH)
#define AH_K1 (2*128*QKPH)
#define AH_V0 (3*128*QKPH)
#define AH_V1 (4*128*QKPH)
#define ATTN_SMEM (5*128*QKPH*2)         // 92160 bytes

#define L2E   1.4426950408889634f
#define EOFF  (-0.42695040888963f)
#define ONES2 0x3C003C00u

__global__ __launch_bounds__(128, 2) void attn_h()
{
    extern __shared__ __half smh[];
    const uint32_t sb = (uint32_t)__cvta_generic_to_shared(smh);

    const int bh = blockIdx.y;
    const int b  = bh >> 4;
    const int h  = bh & 15;
    const int q0 = blockIdx.x * 128;
    const int tid  = threadIdx.x;
    const int wid  = tid >> 5;
    const int lane = tid & 31;
    const int g    = lane >> 2;
    const int tg   = lane & 3;
    const int wm   = wid * 32;

    const int t7   = lane & 7;
    const int aRow = t7 + ((lane >> 3) & 1) * 8;
    const int aCol = (lane >> 4) * 8;
    const int bRow = ((lane >> 4) & 1) * 8 + t7;
    const int bCol = ((lane >> 3) & 1) * 8;
    const int vRow = ((lane >> 3) & 1) * 8 + t7;
    const int vCol = (lane >> 4) * 8;

    const __half* Qg = g_Qh + ((size_t)b*SEQ + q0)*DIM + h*HDIM;
    const __half* Kg = g_Kh + (size_t)b*SEQ*DIM + h*HDIM;
    const __half* Vg = g_Vh + (size_t)b*SEQ*DIM + h*HDIM;

    pdl_wait();

    #pragma unroll
    for (int i = 0; i < 8; i++) {
        int idx = i * 128 + tid;
        int r = idx >> 3, q = idx & 7;
        cpasync16(sb + (uint32_t)(AH_Q  + r*QKPH + q*8)*2, Qg + (size_t)r*DIM + q*8);
        cpasync16(sb + (uint32_t)(AH_K0 + r*QKPH + q*8)*2, Kg + (size_t)r*DIM + q*8);
        cpasync16(sb + (uint32_t)(AH_V0 + r*QKPH + q*8)*2, Vg + (size_t)r*DIM + q*8);
    }
    asm volatile("cp.async.commit_group;" ::: "memory");

    float oacc[2][8][4];
    #pragma unroll
    for (int grp = 0; grp < 2; grp++)
        #pragma unroll
        for (int ni = 0; ni < 8; ni++)
            #pragma unroll
            for (int j = 0; j < 4; j++) oacc[grp][ni][j] = 0.f;
    float lsum[2][4] = {{0.f,0.f,0.f,0.f},{0.f,0.f,0.f,0.f}};
    const uint32_t onesb[2] = { ONES2, ONES2 };

    const int NT = SEQ / 128;
    for (int kt = 0; kt < NT; kt++) {
        asm volatile("cp.async.wait_group 0;" ::: "memory");
        __syncthreads();

        if (kt + 1 < NT) {
            const __half* Kn = Kg + (size_t)(kt + 1) * 128 * DIM;
            const __half* Vn = Vg + (size_t)(kt + 1) * 128 * DIM;
            const uint32_t kdst = ((kt + 1) & 1) ? AH_K1 : AH_K0;
            const uint32_t vdst = ((kt + 1) & 1) ? AH_V1 : AH_V0;
            #pragma unroll
            for (int i = 0; i < 8; i++) {
                int idx = i * 128 + tid;
                int r = idx >> 3, q = idx & 7;
                cpasync16(sb + (uint32_t)(kdst + r*QKPH + q*8)*2, Kn + (size_t)r*DIM + q*8);
                cpasync16(sb + (uint32_t)(vdst + r*QKPH + q*8)*2, Vn + (size_t)r*DIM + q*8);
            }
        }
        asm volatile("cp.async.commit_group;" ::: "memory");

        const uint32_t ksrc = (kt & 1) ? AH_K1 : AH_K0;
        const uint32_t vsrc = (kt & 1) ? AH_V1 : AH_V0;

        // ---- S = Q K^T : both 16-row groups fused over shared K fragments ----
        float sacc[2][16][4];
        #pragma unroll
        for (int grp = 0; grp < 2; grp++)
            #pragma unroll
            for (int ni = 0; ni < 16; ni++)
                #pragma unroll
                for (int j = 0; j < 4; j++) sacc[grp][ni][j] = 0.f;

        #pragma unroll
        for (int kk = 0; kk < 4; kk++) {
            const int kh = kk * 16;
            uint32_t aq0[4], aq1[4];
            ldsm4(aq0, sb + (uint32_t)(AH_Q + (wm + aRow)*QKPH + kh + aCol) * 2);
            ldsm4(aq1, sb + (uint32_t)(AH_Q + (wm + 16 + aRow)*QKPH + kh + aCol) * 2);
            #pragma unroll
            for (int nj = 0; nj < 8; nj++) {
                uint32_t bk[4];
                ldsm4(bk, sb + (uint32_t)(ksrc + (nj*16 + bRow)*QKPH + kh + bCol) * 2);
                mma_f16(sacc[0][2*nj],   aq0, &bk[0]);
                mma_f16(sacc[0][2*nj+1], aq0, &bk[2]);
                mma_f16(sacc[1][2*nj],   aq1, &bk[0]);
                mma_f16(sacc[1][2*nj+1], aq1, &bk[2]);
            }
        }

        // ---- softmax into register P + ones-MMA row sums ----
        uint32_t pa[2][8][4];
        #pragma unroll
        for (int grp = 0; grp < 2; grp++)
            #pragma unroll
            for (int j = 0; j < 8; j++) {
                pa[grp][j][0] = hex2_2(fmaf(sacc[grp][2*j][0],   L2E, EOFF), fmaf(sacc[grp][2*j][1],   L2E, EOFF));
                pa[grp][j][1] = hex2_2(fmaf(sacc[grp][2*j][2],   L2E, EOFF), fmaf(sacc[grp][2*j][3],   L2E, EOFF));
                pa[grp][j][2] = hex2_2(fmaf(sacc[grp][2*j+1][0], L2E, EOFF), fmaf(sacc[grp][2*j+1][1], L2E, EOFF));
                pa[grp][j][3] = hex2_2(fmaf(sacc[grp][2*j+1][2], L2E, EOFF), fmaf(sacc[grp][2*j+1][3], L2E, EOFF));
                mma_f16(lsum[grp], pa[grp][j], onesb);
            }

        // ---- O += P V : V fragments loaded once, shared by both groups ----
        #pragma unroll
        for (int j = 0; j < 8; j++) {
            #pragma unroll
            for (int nj = 0; nj < 4; nj++) {
                uint32_t bv[4];
                ldsm4t(bv, sb + (uint32_t)(vsrc + (j*16 + vRow)*QKPH + nj*16 + vCol) * 2);
                mma_f16(oacc[0][2*nj],   pa[0][j], &bv[0]);
                mma_f16(oacc[0][2*nj+1], pa[0][j], &bv[2]);
                mma_f16(oacc[1][2*nj],   pa[1][j], &bv[0]);
                mma_f16(oacc[1][2*nj+1], pa[1][j], &bv[2]);
            }
        }
    }

    __half* Og = g_Oh + ((size_t)b*SEQ + q0)*DIM + h*HDIM;
    #pragma unroll
    for (int grp = 0; grp < 2; grp++) {
        const float inv0 = 1.0f / lsum[grp][0];
        const float inv1 = 1.0f / lsum[grp][2];
        const int rowb = wm + grp * 16;
        #pragma unroll
        for (int ni = 0; ni < 8; ni++) {
            const int col = ni * 8 + 2 * tg;
            *(__half2*)(Og + (size_t)(rowb + g)*DIM + col) =
                __floats2half2_rn(oacc[grp][ni][0]*inv0, oacc[grp][ni][1]*inv0);
            *(__half2*)(Og + (size_t)(rowb + 8 + g)*DIM + col) =
                __floats2half2_rn(oacc[grp][ni][2]*inv1, oacc[grp][ni][3]*inv1);
        }
    }
}

// ---------------------------------------------------------------------------
// PDL launch helper
// ---------------------------------------------------------------------------
template <typename K, typename... Args>
static void launch_pdl(K kern, dim3 grid, dim3 block, size_t smem, Args... args) {
    cudaLaunchConfig_t cfg = {};
    cfg.gridDim = grid;
    cfg.blockDim = block;
    cfg.dynamicSmemBytes = smem;
    cfg.stream = 0;
    cudaLaunchAttribute attr[1];
    attr[0].id = cudaLaunchAttributeProgrammaticStreamSerialization;
    attr[0].val.programmaticStreamSerializationAllowed = 1;
    cfg.attrs = attr;
    cfg.numAttrs = 1;
    cudaLaunchKernelEx(&cfg, kern, args...);
}

// ---------------------------------------------------------------------------
extern "C" void kernel_launch(void* const* d_in, const int* in_sizes, int n_in,
                              void* d_out, int out_size)
{
    const float* x    = (const float*)d_in[0];
    const float* Wq   = (const float*)d_in[1];
    const float* bq   = (const float*)d_in[2];
    const float* Wk   = (const float*)d_in[3];
    const float* bk   = (const float*)d_in[4];
    const float* Wv   = (const float*)d_in[5];
    const float* bv   = (const float*)d_in[6];
    const float* Wo   = (const float*)d_in[7];
    const float* bo   = (const float*)d_in[8];
    const float* qn_g = (const float*)d_in[9];
    const float* qn_b = (const float*)d_in[10];
    const float* kn_g = (const float*)d_in[11];
    const float* kn_b = (const float*)d_in[12];
    const float* vn_g = (const float*)d_in[13];
    const float* vn_b = (const float*)d_in[14];
    const float* on_g = (const float*)d_in[15];
    const float* on_b = (const float*)d_in[16];
    float* out = (float*)d_out;

    __half *Xh, *Wh, *Oh, *Fh;
    float *F;
    cudaGetSymbolAddress((void**)&Xh, g_Xh);
    cudaGetSymbolAddress((void**)&Wh, g_Wh);
    cudaGetSymbolAddress((void**)&Oh, g_Oh);
    cudaGetSymbolAddress((void**)&Fh, g_Fh);
    cudaGetSymbolAddress((void**)&F,  g_F);

    cudaFuncSetAttribute(gemm_h<__half>, cudaFuncAttributeMaxDynamicSharedMemorySize, GEMM_SMEM);
    cudaFuncSetAttribute(gemm_h<float>,  cudaFuncAttributeMaxDynamicSharedMemorySize, GEMM_SMEM);
    cudaFuncSetAttribute(attn_h, cudaFuncAttributeMaxDynamicSharedMemorySize, ATTN_SMEM);

    conv_h<<<CONV_TOT / 1024, 256>>>((const float4*)x, (const float4*)Wq,
                                     (const float4*)Wk, (const float4*)Wv,
                                     (const float4*)Wo);

    launch_pdl(gemm_h<__half>, dim3(DIM/128, MROWS/128, 3), dim3(256), (size_t)GEMM_SMEM,
               (const __half*)Xh, (const __half*)Wh, bq, bk, bv, Fh);
    launch_pdl(ln3_h, dim3(MROWS/8, 3), dim3(256), (size_t)0,
               qn_g, qn_b, kn_g, kn_b, vn_g, vn_b);
    launch_pdl(attn_h, dim3(SEQ/128, BATCH*NHEAD), dim3(128), (size_t)ATTN_SMEM);
    launch_pdl(gemm_h<float>, dim3(DIM/128, MROWS/128, 1), dim3(256), (size_t)GEMM_SMEM,
               (const __half*)Oh, (const __half*)(Wh + 3*(size_t)DIM*DIM), bo, bo, bo, F);
    launch_pdl(ln_f, dim3(MROWS/8), dim3(256), (size_t)0,
               (const float*)F, out, on_g, on_b);
}